// round 1
// baseline (speedup 1.0000x reference)
#include <cuda_runtime.h>
#include <cstdint>
#include <cstddef>

// Problem constants (fixed shapes for this problem instance)
#define TOKENS   16384            // b*n = 8*2048
#define DIM      1024
#define NE       64
#define CAP      40
#define TAU      0.7f
#define DISP_SZ  ((size_t)TOKENS * NE * CAP)   // 41,943,040 floats per output tensor

// ---------------- static device scratch (no allocations allowed) ----------------
__device__ float              g_logits[(size_t)TOKENS * NE];   // 4 MB
__device__ float              g_pfull [(size_t)TOKENS * NE];   // 4 MB (normalized prob if selected else 0)
__device__ unsigned long long g_mask  [TOKENS];                // selected-expert bitmask per token
__device__ int                g_cnt   [(TOKENS / 32) * NE];    // per-32-token-chunk expert counts
__device__ int                g_off   [(TOKENS / 32) * NE];    // exclusive prefix offsets

// ---------------- packed f32x2 helpers (FFMA2: 2x fp32 FMA throughput) ----------------
static __device__ __forceinline__ unsigned long long pk2(float a, float b) {
    unsigned long long r;
    asm("mov.b64 %0, {%1, %2};" : "=l"(r) : "f"(a), "f"(b));
    return r;
}
static __device__ __forceinline__ unsigned long long ffma2(unsigned long long a,
                                                           unsigned long long b,
                                                           unsigned long long c) {
    unsigned long long d;
    asm("fma.rn.f32x2 %0, %1, %2, %3;" : "=l"(d) : "l"(a), "l"(b), "l"(c));
    return d;
}
static __device__ __forceinline__ float2 upk2(unsigned long long a) {
    float2 r;
    asm("mov.b64 {%0, %1}, %2;" : "=f"(r.x), "=f"(r.y) : "l"(a));
    return r;
}

// ---------------- Kernel 1: fused output-zeroing + fp32 GEMM (logits) ----------------
// Grid = GEMM_BLOCKS gemm tiles + NZ zero blocks. 2 blocks/SM co-resident -> the
// DRAM-bound zero-fill overlaps with the FMA-bound GEMM across the whole chip.
#define BT 128                    // tokens per gemm block
#define KC 32                     // k-chunk
#define XS 132                    // x smem row stride (floats), pad for bank spread, 16B-aligned
#define WS 68                     // w smem row stride
#define GEMM_BLOCKS (TOKENS / BT) // 128
#define NZ 168                    // zero-fill blocks (total grid 296 = 2*148)

__global__ void __launch_bounds__(256, 2)
k_gemm_zero(const float* __restrict__ x, const float* __restrict__ wg,
            float* __restrict__ out)
{
    if (blockIdx.x >= GEMM_BLOCKS) {
        // ---- zero-fill dispatch+combine (335 MB) with float4 stores ----
        const size_t nz4 = (2 * DISP_SZ) / 4;
        float4 z = make_float4(0.f, 0.f, 0.f, 0.f);
        float4* o4 = (float4*)out;
        const size_t stride = (size_t)NZ * 256;
        for (size_t i = (size_t)(blockIdx.x - GEMM_BLOCKS) * 256 + threadIdx.x;
             i < nz4; i += stride)
            o4[i] = z;
        return;
    }

    // ---- GEMM tile: 128 tokens x 64 experts, thread tile 4 tokens x 8 experts ----
    __shared__ float xs[KC * XS];   // transposed x chunk: xs[k][token]
    __shared__ float ws[KC * WS];   // w chunk: ws[k][expert]

    const int tid = threadIdx.x;
    const int tg  = tid >> 3;          // 0..31 token group (4 tokens each)
    const int eg  = tid & 7;           // 0..7  expert group (8 experts each)
    const int tt  = tg * 4;
    const int ee  = eg * 8;
    const int tok0 = blockIdx.x * BT;

    unsigned long long acc[4][4];      // [token][expert-pair] packed f32x2
#pragma unroll
    for (int i = 0; i < 4; i++)
#pragma unroll
        for (int j = 0; j < 4; j++) acc[i][j] = 0ull;

    for (int k0 = 0; k0 < DIM; k0 += KC) {
        // load x tile (coalesced global float4 along k), store transposed
#pragma unroll
        for (int r = 0; r < 4; r++) {
            int idx = r * 256 + tid;
            int t = idx >> 3, j = idx & 7;
            float4 v = *(const float4*)(x + (size_t)(tok0 + t) * DIM + k0 + 4 * j);
            xs[(4 * j + 0) * XS + t] = v.x;
            xs[(4 * j + 1) * XS + t] = v.y;
            xs[(4 * j + 2) * XS + t] = v.z;
            xs[(4 * j + 3) * XS + t] = v.w;
        }
        // load w tile
#pragma unroll
        for (int r = 0; r < 2; r++) {
            int idx = r * 256 + tid;
            int kk = idx >> 4, c4 = idx & 15;
            float4 v = *(const float4*)(wg + (size_t)(k0 + kk) * NE + 4 * c4);
            *(float4*)&ws[kk * WS + 4 * c4] = v;
        }
        __syncthreads();

#pragma unroll
        for (int kk = 0; kk < KC; kk++) {
            float4 xa = *(const float4*)&xs[kk * XS + tt];        // 4 tokens (broadcast)
            float4 wa = *(const float4*)&ws[kk * WS + ee];        // experts ee..ee+3
            float4 wb = *(const float4*)&ws[kk * WS + ee + 4];    // experts ee+4..ee+7
            unsigned long long wp[4];
            wp[0] = pk2(wa.x, wa.y); wp[1] = pk2(wa.z, wa.w);
            wp[2] = pk2(wb.x, wb.y); wp[3] = pk2(wb.z, wb.w);
            unsigned long long xd[4];
            xd[0] = pk2(xa.x, xa.x); xd[1] = pk2(xa.y, xa.y);
            xd[2] = pk2(xa.z, xa.z); xd[3] = pk2(xa.w, xa.w);
#pragma unroll
            for (int t = 0; t < 4; t++)
#pragma unroll
                for (int p = 0; p < 4; p++)
                    acc[t][p] = ffma2(xd[t], wp[p], acc[t][p]);
        }
        __syncthreads();
    }

    // write logits [token][expert]
#pragma unroll
    for (int t = 0; t < 4; t++) {
        float2 r0 = upk2(acc[t][0]), r1 = upk2(acc[t][1]);
        float2 r2 = upk2(acc[t][2]), r3 = upk2(acc[t][3]);
        float* dst = g_logits + (size_t)(tok0 + tt + t) * NE + ee;
        *(float4*)dst       = make_float4(r0.x, r0.y, r1.x, r1.y);
        *(float4*)(dst + 4) = make_float4(r2.x, r2.y, r3.x, r3.y);
    }
}

// ---------------- Kernel 2: routing (softmax + top-8 + tau cutoff) + chunk counts ----------------
// 1 warp per token, 32 tokens per block. Emits per-token selected-expert bitmask,
// normalized probs (g_pfull), and per-chunk per-expert counts.
__global__ void __launch_bounds__(1024)
k_route()
{
    const int tid  = threadIdx.x;
    const int wid  = tid >> 5;
    const int lane = tid & 31;
    const int t    = blockIdx.x * 32 + wid;
    __shared__ unsigned long long smask[32];

    const float* lg = g_logits + (size_t)t * NE;
    float v0 = lg[lane];
    float v1 = lg[lane + 32];

    // softmax over 64 gates
    float mx = fmaxf(v0, v1);
#pragma unroll
    for (int o = 16; o > 0; o >>= 1) mx = fmaxf(mx, __shfl_xor_sync(0xffffffffu, mx, o));
    float p0 = expf(v0 - mx), p1 = expf(v1 - mx);
    float s = p0 + p1;
#pragma unroll
    for (int o = 16; o > 0; o >>= 1) s += __shfl_xor_sync(0xffffffffu, s, o);
    p0 /= s; p1 /= s;

    // iterative warp argmax top-8, ties -> lower expert index (matches lax.top_k)
    bool u0 = false, u1 = false;
    float topv[8]; int topi[8];
#pragma unroll
    for (int j = 0; j < 8; j++) {
        float cv; int ci;
        if (!u0 && (u1 || p0 >= p1)) { cv = p0; ci = lane; }
        else if (!u1)                { cv = p1; ci = lane + 32; }
        else                         { cv = -1.f; ci = 1 << 20; }
#pragma unroll
        for (int o = 16; o > 0; o >>= 1) {
            float ov = __shfl_down_sync(0xffffffffu, cv, o);
            int   oi = __shfl_down_sync(0xffffffffu, ci, o);
            if (ov > cv || (ov == cv && oi < ci)) { cv = ov; ci = oi; }
        }
        cv = __shfl_sync(0xffffffffu, cv, 0);
        ci = __shfl_sync(0xffffffffu, ci, 0);
        topv[j] = cv; topi[j] = ci;
        if (ci == lane)            u0 = true;
        else if (ci == lane + 32)  u1 = true;
    }

    // k* from inclusive cumsum threshold (monotone), top-1 always kept
    float cs = 0.f; int kstar = 0;
#pragma unroll
    for (int j = 0; j < 8; j++) { cs += topv[j]; kstar += (cs < TAU) ? 1 : 0; }
    if (kstar < 1) kstar = 1;

    float ssum = 0.f;
    for (int j = 0; j < kstar; j++) ssum += topv[j];
    float den = fmaxf(ssum, 1e-7f);

    float o0 = 0.f, o1 = 0.f;
    unsigned long long m = 0ull;
    for (int j = 0; j < kstar; j++) {
        if (topi[j] == lane)      o0 = topv[j] / den;
        if (topi[j] == lane + 32) o1 = topv[j] / den;
        m |= 1ull << topi[j];
    }
    g_pfull[(size_t)t * NE + lane]      = o0;
    g_pfull[(size_t)t * NE + lane + 32] = o1;
    if (lane == 0) { smask[wid] = m; g_mask[t] = m; }
    __syncthreads();

    // per-chunk per-expert counts (chunk = this block's 32 tokens)
    if (tid < NE) {
        int c = 0;
#pragma unroll
        for (int i = 0; i < 32; i++) c += (int)((smask[i] >> tid) & 1ull);
        g_cnt[blockIdx.x * NE + tid] = c;
    }
}

// ---------------- Kernel 3: exclusive scan over chunks per expert + load-balance loss ----------------
__global__ void k_scan_loss(float* __restrict__ out)
{
    const int e = threadIdx.x;   // 64 threads
    int run = 0;
    for (int c = 0; c < TOKENS / 32; c++) {
        g_off[c * NE + e] = run;
        run += g_cnt[c * NE + e];
    }
    float usage = (float)(run < CAP ? run : CAP);
    __shared__ float su[NE];
    su[e] = usage;
    __syncthreads();
    if (e == 0) {
        float sum = 0.f;
        for (int i = 0; i < NE; i++) sum += su[i];
        float mean = sum / (float)NE;
        float var = 0.f;
        for (int i = 0; i < NE; i++) { float d = su[i] - mean; var += d * d; }
        var /= (float)NE;
        out[2 * DISP_SZ] = (sum > 0.f) ? var / (mean + 1e-8f) : 0.f;
    }
}

// ---------------- Kernel 4: scatter the surviving (pos < cap) assignments ----------------
__global__ void k_scatter(float* __restrict__ out)
{
    const int e = threadIdx.x;     // expert
    const int c = blockIdx.x;      // 32-token chunk
    int ctr = g_off[c * NE + e];
    if (ctr >= CAP) return;        // whole chunk past capacity for this expert
    const int t0 = c * 32;
    for (int i = 0; i < 32; i++) {
        unsigned long long m = g_mask[t0 + i];
        if ((m >> e) & 1ull) {
            if (ctr >= CAP) break;
            size_t o = ((size_t)(t0 + i) * NE + e) * CAP + (size_t)ctr;
            out[o] = 1.0f;                                              // dispatch
            out[DISP_SZ + o] = g_pfull[(size_t)(t0 + i) * NE + e];      // combine
            ctr++;
        }
    }
}

// ---------------- launch ----------------
extern "C" void kernel_launch(void* const* d_in, const int* in_sizes, int n_in,
                              void* d_out, int out_size)
{
    const float* x  = (const float*)d_in[0];
    const float* wg = (const float*)d_in[1];
    float* out = (float*)d_out;

    k_gemm_zero<<<GEMM_BLOCKS + NZ, 256>>>(x, wg, out);
    k_route<<<TOKENS / 32, 1024>>>();
    k_scan_loss<<<1, NE>>>(out);
    k_scatter<<<TOKENS / 32, NE>>>(out);
}

// round 4
// speedup vs baseline: 1.0990x; 1.0990x over previous
#include <cuda_runtime.h>
#include <cstdint>
#include <cstddef>

// Problem constants
#define TOKENS   16384            // b*n = 8*2048
#define DIM      1024
#define NE       64
#define CAP      40
#define TAU      0.7f
#define DISP_SZ  ((size_t)TOKENS * NE * CAP)   // floats per output tensor

// ---------------- static device scratch ----------------
__device__ float              g_pfull[(size_t)TOKENS * NE];   // normalized prob if selected else 0
__device__ unsigned long long g_mask [TOKENS];                // selected-expert bitmask per token
__device__ int                g_cnt  [(TOKENS / 128) * NE];   // per-128-token-chunk expert counts

// ---------------- packed f32x2 helpers ----------------
static __device__ __forceinline__ unsigned long long pk2(float a, float b) {
    unsigned long long r;
    asm("mov.b64 %0, {%1, %2};" : "=l"(r) : "f"(a), "f"(b));
    return r;
}
static __device__ __forceinline__ unsigned long long ffma2(unsigned long long a,
                                                           unsigned long long b,
                                                           unsigned long long c) {
    unsigned long long d;
    asm("fma.rn.f32x2 %0, %1, %2, %3;" : "=l"(d) : "l"(a), "l"(b), "l"(c));
    return d;
}
static __device__ __forceinline__ float2 upk2(unsigned long long a) {
    float2 r;
    asm("mov.b64 {%0, %1}, %2;" : "=f"(r.x), "=f"(r.y) : "l"(a));
    return r;
}

// =====================================================================
// Kernel 1: fused  [zero-fill 335MB output]  +  [GEMM logits -> smem]
//           +  [softmax/top-8/tau routing]  +  [per-chunk expert counts]
// Grid = 128 gemm blocks + NZ zero blocks, 256 thr, 2 blocks/SM resident
// =====================================================================
#define BT 128                     // tokens per gemm block (= chunk size)
#define KC 32                      // k-chunk
#define XS 132                     // x smem row stride (floats)
#define WS 68                      // w smem row stride
#define LSS 68                     // logits smem row stride
#define GEMM_BLOCKS (TOKENS / BT)  // 128
#define NZ 168                     // zero blocks -> total grid 296

__global__ void __launch_bounds__(256, 2)
k_main(const float* __restrict__ x, const float* __restrict__ wg,
       float* __restrict__ out)
{
    __shared__ float sbuf[BT * LSS];            // 34816 B; reused: [xs|ws] then logits
    __shared__ unsigned long long smask[BT];

    const int tid = threadIdx.x;

    if (blockIdx.x >= GEMM_BLOCKS) {
        // ---- zero-fill: contiguous ~2MB slab per block, streaming float4 stores
        //      (__stwt: no L2 allocation -> don't churn L2 under the GEMM) ----
        const size_t nz4 = (2 * DISP_SZ) / 4;
        const size_t per = (nz4 + NZ - 1) / NZ;
        const int zb = blockIdx.x - GEMM_BLOCKS;
        size_t lo = (size_t)zb * per;
        size_t hi = lo + per; if (hi > nz4) hi = nz4;
        float4 z = make_float4(0.f, 0.f, 0.f, 0.f);
        float4* o4 = (float4*)out;
        for (size_t i = lo + tid; i < hi; i += 256) __stwt(o4 + i, z);
        return;
    }

    float* xs = sbuf;              // KC*XS = 4224 floats
    float* ws = sbuf + KC * XS;    // KC*WS = 2176 floats (total 6400 <= 8704)

    const int tg  = tid >> 3;          // 0..31 token group (4 tokens)
    const int eg  = tid & 7;           // 0..7  expert group (8 experts)
    const int tt  = tg * 4;
    const int ee  = eg * 8;
    const int tok0 = blockIdx.x * BT;

    unsigned long long acc[4][4];
#pragma unroll
    for (int i = 0; i < 4; i++)
#pragma unroll
        for (int j = 0; j < 4; j++) acc[i][j] = 0ull;

    for (int k0 = 0; k0 < DIM; k0 += KC) {
#pragma unroll
        for (int r = 0; r < 4; r++) {
            int idx = r * 256 + tid;
            int t = idx >> 3, j = idx & 7;
            float4 v = *(const float4*)(x + (size_t)(tok0 + t) * DIM + k0 + 4 * j);
            xs[(4 * j + 0) * XS + t] = v.x;
            xs[(4 * j + 1) * XS + t] = v.y;
            xs[(4 * j + 2) * XS + t] = v.z;
            xs[(4 * j + 3) * XS + t] = v.w;
        }
#pragma unroll
        for (int r = 0; r < 2; r++) {
            int idx = r * 256 + tid;
            int kk = idx >> 4, c4 = idx & 15;
            float4 v = *(const float4*)(wg + (size_t)(k0 + kk) * NE + 4 * c4);
            *(float4*)&ws[kk * WS + 4 * c4] = v;
        }
        __syncthreads();

#pragma unroll
        for (int kk = 0; kk < KC; kk++) {
            float4 xa = *(const float4*)&xs[kk * XS + tt];
            float4 wa = *(const float4*)&ws[kk * WS + ee];
            float4 wb = *(const float4*)&ws[kk * WS + ee + 4];
            unsigned long long wp[4];
            wp[0] = pk2(wa.x, wa.y); wp[1] = pk2(wa.z, wa.w);
            wp[2] = pk2(wb.x, wb.y); wp[3] = pk2(wb.z, wb.w);
            unsigned long long xd[4];
            xd[0] = pk2(xa.x, xa.x); xd[1] = pk2(xa.y, xa.y);
            xd[2] = pk2(xa.z, xa.z); xd[3] = pk2(xa.w, xa.w);
#pragma unroll
            for (int t = 0; t < 4; t++)
#pragma unroll
                for (int p = 0; p < 4; p++)
                    acc[t][p] = ffma2(xd[t], wp[p], acc[t][p]);
        }
        __syncthreads();
    }

    // ---- write logits into smem (reuses xs/ws space; all reads are done) ----
#pragma unroll
    for (int t = 0; t < 4; t++) {
        float2 r0 = upk2(acc[t][0]), r1 = upk2(acc[t][1]);
        float2 r2 = upk2(acc[t][2]), r3 = upk2(acc[t][3]);
        float* dst = sbuf + (size_t)(tt + t) * LSS + ee;
        *(float4*)dst       = make_float4(r0.x, r0.y, r1.x, r1.y);
        *(float4*)(dst + 4) = make_float4(r2.x, r2.y, r3.x, r3.y);
    }
    __syncthreads();

    // ---- routing: warp wid handles 16 tokens ----
    const int wid  = tid >> 5;
    const int lane = tid & 31;

    for (int it = 0; it < 16; it++) {
        const int t = wid * 16 + it;
        float v0 = sbuf[t * LSS + lane];
        float v1 = sbuf[t * LSS + 32 + lane];

        // softmax over 64 gates
        float mx = fmaxf(v0, v1);
#pragma unroll
        for (int o = 16; o > 0; o >>= 1) mx = fmaxf(mx, __shfl_xor_sync(0xffffffffu, mx, o));
        float p0 = expf(v0 - mx), p1 = expf(v1 - mx);
        float s = p0 + p1;
#pragma unroll
        for (int o = 16; o > 0; o >>= 1) s += __shfl_xor_sync(0xffffffffu, s, o);
        p0 /= s; p1 /= s;

        // iterative warp argmax top-8, ties -> lower expert index
        bool u0 = false, u1 = false;
        float topv[8]; int topi[8];
#pragma unroll
        for (int j = 0; j < 8; j++) {
            float cv; int ci;
            if (!u0 && (u1 || p0 >= p1)) { cv = p0; ci = lane; }
            else if (!u1)                { cv = p1; ci = lane + 32; }
            else                         { cv = -1.f; ci = 1 << 20; }
#pragma unroll
            for (int o = 16; o > 0; o >>= 1) {
                float ov = __shfl_down_sync(0xffffffffu, cv, o);
                int   oi = __shfl_down_sync(0xffffffffu, ci, o);
                if (ov > cv || (ov == cv && oi < ci)) { cv = ov; ci = oi; }
            }
            cv = __shfl_sync(0xffffffffu, cv, 0);
            ci = __shfl_sync(0xffffffffu, ci, 0);
            topv[j] = cv; topi[j] = ci;
            if (ci == lane)            u0 = true;
            else if (ci == lane + 32)  u1 = true;
        }

        // k* via inclusive-cumsum threshold (fully unrolled -> regs only)
        float cs = 0.f; int kstar = 0;
#pragma unroll
        for (int j = 0; j < 8; j++) { cs += topv[j]; kstar += (cs < TAU) ? 1 : 0; }
        if (kstar < 1) kstar = 1;

        float ssum = 0.f;
#pragma unroll
        for (int j = 0; j < 8; j++) if (j < kstar) ssum += topv[j];
        float den = fmaxf(ssum, 1e-7f);

        float o0 = 0.f, o1 = 0.f;
        unsigned long long m = 0ull;
#pragma unroll
        for (int j = 0; j < 8; j++) {
            if (j < kstar) {
                if (topi[j] == lane)      o0 = topv[j] / den;
                if (topi[j] == lane + 32) o1 = topv[j] / den;
                m |= 1ull << topi[j];
            }
        }
        g_pfull[(size_t)(tok0 + t) * NE + lane]      = o0;
        g_pfull[(size_t)(tok0 + t) * NE + lane + 32] = o1;
        if (lane == 0) { smask[t] = m; g_mask[tok0 + t] = m; }
    }
    __syncthreads();

    // ---- per-chunk (=this block) expert counts ----
    if (tid < NE) {
        int c = 0;
#pragma unroll 8
        for (int i = 0; i < BT; i++) c += (int)((smask[i] >> tid) & 1ull);
        g_cnt[blockIdx.x * NE + tid] = c;
    }
}

// =====================================================================
// Kernel 2: finalize — per-expert parallel prefix over 128 chunk counts,
//           load-balance loss, deterministic ballot scatter. 1 block.
// =====================================================================
#define NCHUNK (TOKENS / BT)   // 128

__global__ void __launch_bounds__(1024)
k_finalize(float* __restrict__ out)
{
    __shared__ int   soff[NCHUNK * NE];   // exclusive offsets [chunk][expert], 32 KB
    __shared__ float susage[NE];

    const int tid  = threadIdx.x;
    const int lane = tid & 31;
    const int w    = tid >> 5;            // 32 warps; warp w -> experts w, w+32

    // ---- 1. per-expert exclusive scan over chunks (4 warp-scans) ----
    for (int e = w; e < NE; e += 32) {
        int run = 0;
#pragma unroll
        for (int g = 0; g < 4; g++) {
            int c = g * 32 + lane;
            int v = g_cnt[c * NE + e];
            int incl = v;
#pragma unroll
            for (int o = 1; o < 32; o <<= 1) {
                int nv = __shfl_up_sync(0xffffffffu, incl, o);
                if (lane >= o) incl += nv;
            }
            soff[c * NE + e] = run + incl - v;
            run += __shfl_sync(0xffffffffu, incl, 31);
        }
        if (lane == 0) susage[e] = (float)(run < CAP ? run : CAP);
    }
    __syncthreads();

    // ---- 2. load-balance loss ----
    if (w == 0) {
        float u0 = susage[lane], u1 = susage[lane + 32];
        float s = u0 + u1;
#pragma unroll
        for (int o = 16; o > 0; o >>= 1) s += __shfl_xor_sync(0xffffffffu, s, o);
        float mean = s / (float)NE;
        float d0 = u0 - mean, d1 = u1 - mean;
        float v = d0 * d0 + d1 * d1;
#pragma unroll
        for (int o = 16; o > 0; o >>= 1) v += __shfl_xor_sync(0xffffffffu, v, o);
        float var = v / (float)NE;
        if (lane == 0)
            out[2 * DISP_SZ] = (s > 0.f) ? var / (mean + 1e-8f) : 0.f;
    }

    // ---- 3. scatter survivors (pos < CAP), deterministic via ballot ----
    for (int e = w; e < NE; e += 32) {
        for (int c = 0; c < NCHUNK; c++) {
            int base = soff[c * NE + e];
            if (base >= CAP) break;            // offsets monotone per expert
#pragma unroll
            for (int sg = 0; sg < 4; sg++) {
                int t = c * BT + sg * 32 + lane;
                unsigned long long m = g_mask[t];
                int bit = (int)((m >> e) & 1ull);
                unsigned bal = __ballot_sync(0xffffffffu, bit);
                int pos = base + __popc(bal & ((1u << lane) - 1u));
                if (bit && pos < CAP) {
                    size_t o = ((size_t)t * NE + e) * CAP + (size_t)pos;
                    out[o] = 1.0f;
                    out[DISP_SZ + o] = g_pfull[(size_t)t * NE + e];
                }
                base += __popc(bal);
                if (base >= CAP) break;        // warp-uniform
            }
        }
    }
}

// ---------------- launch ----------------
extern "C" void kernel_launch(void* const* d_in, const int* in_sizes, int n_in,
                              void* d_out, int out_size)
{
    const float* x  = (const float*)d_in[0];
    const float* wg = (const float*)d_in[1];
    float* out = (float*)d_out;

    k_main<<<GEMM_BLOCKS + NZ, 256>>>(x, wg, out);
    k_finalize<<<1, 1024>>>(out);
}

// round 6
// speedup vs baseline: 1.6504x; 1.5017x over previous
#include <cuda_runtime.h>
#include <cstdint>
#include <cstddef>

// Problem constants
#define TOKENS   16384            // b*n = 8*2048
#define DIM      1024
#define NE       64
#define CAP      40
#define TAU      0.7f
#define DISP_SZ  ((size_t)TOKENS * NE * CAP)   // floats per output tensor

#define BT      128                  // tokens per gemm block (= chunk)
#define NCHUNK  (TOKENS / BT)        // 128
#define KC      16                   // k-chunk (double-buffered)
#define XS      132                  // xs stride (floats)
#define WS      68                   // ws stride (floats)
#define LSS     68                   // logits stride (floats)
#define GEMM_BLOCKS NCHUNK           // 128
#define NZ      168                  // zero-only blocks -> grid 296
#define PRE_F4  65536                // 1MB zeroed by k_pre (tail of output)

// ---------------- static device scratch ----------------
__device__ float              g_pc  [(size_t)TOKENS * 8];     // compact probs, expert-rank order
__device__ unsigned long long g_mask[TOKENS];                 // selected-expert bitmask
__device__ int                g_cnt [NE * NCHUNK];            // [e][chunk] counts
__device__ int                g_off [NCHUNK * NE];            // [chunk][e] exclusive offsets

// ---------------- packed f32x2 helpers ----------------
static __device__ __forceinline__ unsigned long long pk2(float a, float b) {
    unsigned long long r;
    asm("mov.b64 %0, {%1, %2};" : "=l"(r) : "f"(a), "f"(b));
    return r;
}
static __device__ __forceinline__ void ffma2(unsigned long long& d,
                                             unsigned long long a,
                                             unsigned long long b) {
    asm("fma.rn.f32x2 %0, %1, %2, %0;" : "+l"(d) : "l"(a), "l"(b));
}
static __device__ __forceinline__ float2 upk2(unsigned long long a) {
    float2 r;
    asm("mov.b64 {%0, %1}, %2;" : "=f"(r.x), "=f"(r.y) : "l"(a));
    return r;
}

// =====================================================================
// Kernel 0: pre — zero the tail 1MB of output (makes k_main launch #6 for ncu)
// =====================================================================
__global__ void k_pre(float* __restrict__ out)
{
    const size_t base = (2 * DISP_SZ) / 4 - PRE_F4;
    float4 z = make_float4(0.f, 0.f, 0.f, 0.f);
    float4* o4 = (float4*)out;
    for (size_t i = (size_t)blockIdx.x * 256 + threadIdx.x; i < PRE_F4; i += 32 * 256)
        o4[base + i] = z;
}

// =====================================================================
// Kernel 1: fused [zero-fill] + [double-buffered GEMM] + [per-thread routing]
// =====================================================================
__global__ void __launch_bounds__(256, 2)
k_main(const float* __restrict__ x, const float* __restrict__ wg,
       float* __restrict__ out)
{
    __shared__ float sbuf[BT * LSS];            // 34816B: gemm double-buffers, then logits
    __shared__ unsigned long long smask[BT];

    const int tid = threadIdx.x;

    if (blockIdx.x >= GEMM_BLOCKS) {
        // ---- zero-fill: contiguous slab per block ----
        const size_t nz4 = (2 * DISP_SZ) / 4 - PRE_F4;
        const size_t per = (nz4 + NZ - 1) / NZ;
        const int zb = blockIdx.x - GEMM_BLOCKS;
        size_t lo = (size_t)zb * per;
        size_t hi = lo + per; if (hi > nz4) hi = nz4;
        float4 z = make_float4(0.f, 0.f, 0.f, 0.f);
        float4* o4 = (float4*)out;
        for (size_t i = lo + tid; i < hi; i += 256) o4[i] = z;
        return;
    }

    // ---------------- GEMM: 128 tokens x 64 experts, double-buffered smem ----------------
    // buffer b at sbuf + b*3200:  xs [0,2112) = [k][token],  ws [2112,3200) = [k][expert]
    const int tg  = tid >> 3;          // 0..31 token group (4 tokens)
    const int eg  = tid & 7;           // 0..7  expert group (8 experts)
    const int tt  = tg * 4;
    const int ee  = eg * 8;
    const int tok0 = blockIdx.x * BT;

    // per-chunk load mapping
    const int lt  = tid >> 2;          // token for x loads (2 float4/thread)
    const int lj  = tid & 3;           // float4 index within 16-float k-slice
    const int wkk = tid >> 4;          // k row for w load (1 float4/thread)
    const int wc4 = tid & 15;

    unsigned long long acc[4][4];
#pragma unroll
    for (int i = 0; i < 4; i++)
#pragma unroll
        for (int j = 0; j < 4; j++) acc[i][j] = 0ull;

    float4 rx0, rx1, rw;
    // prologue: load chunk 0
    rx0 = *(const float4*)(x + (size_t)(tok0 + lt) * DIM + 0 + 4 * lj);
    rx1 = *(const float4*)(x + (size_t)(tok0 + lt + 64) * DIM + 0 + 4 * lj);
    rw  = *(const float4*)(wg + (size_t)wkk * NE + 4 * wc4);
    {
        float* xs = sbuf;
        float* ws = sbuf + 2112;
        xs[(4*lj+0)*XS + lt] = rx0.x; xs[(4*lj+1)*XS + lt] = rx0.y;
        xs[(4*lj+2)*XS + lt] = rx0.z; xs[(4*lj+3)*XS + lt] = rx0.w;
        xs[(4*lj+0)*XS + lt+64] = rx1.x; xs[(4*lj+1)*XS + lt+64] = rx1.y;
        xs[(4*lj+2)*XS + lt+64] = rx1.z; xs[(4*lj+3)*XS + lt+64] = rx1.w;
        *(float4*)&ws[wkk * WS + 4 * wc4] = rw;
    }
    __syncthreads();

    for (int kc = 0; kc < DIM / KC; kc++) {
        const float* xs = sbuf + (kc & 1) * 3200;
        const float* ws = xs + 2112;

        if (kc < DIM / KC - 1) {       // issue next-chunk global loads before compute
            int k0 = (kc + 1) * KC;
            rx0 = *(const float4*)(x + (size_t)(tok0 + lt) * DIM + k0 + 4 * lj);
            rx1 = *(const float4*)(x + (size_t)(tok0 + lt + 64) * DIM + k0 + 4 * lj);
            rw  = *(const float4*)(wg + (size_t)(k0 + wkk) * NE + 4 * wc4);
        }

#pragma unroll
        for (int kk = 0; kk < KC; kk++) {
            float4 xa = *(const float4*)&xs[kk * XS + tt];
            float4 wa = *(const float4*)&ws[kk * WS + ee];
            float4 wb = *(const float4*)&ws[kk * WS + ee + 4];
            unsigned long long wp0 = pk2(wa.x, wa.y), wp1 = pk2(wa.z, wa.w);
            unsigned long long wp2 = pk2(wb.x, wb.y), wp3 = pk2(wb.z, wb.w);
            unsigned long long xd0 = pk2(xa.x, xa.x), xd1 = pk2(xa.y, xa.y);
            unsigned long long xd2 = pk2(xa.z, xa.z), xd3 = pk2(xa.w, xa.w);
            ffma2(acc[0][0], xd0, wp0); ffma2(acc[0][1], xd0, wp1);
            ffma2(acc[0][2], xd0, wp2); ffma2(acc[0][3], xd0, wp3);
            ffma2(acc[1][0], xd1, wp0); ffma2(acc[1][1], xd1, wp1);
            ffma2(acc[1][2], xd1, wp2); ffma2(acc[1][3], xd1, wp3);
            ffma2(acc[2][0], xd2, wp0); ffma2(acc[2][1], xd2, wp1);
            ffma2(acc[2][2], xd2, wp2); ffma2(acc[2][3], xd2, wp3);
            ffma2(acc[3][0], xd3, wp0); ffma2(acc[3][1], xd3, wp1);
            ffma2(acc[3][2], xd3, wp2); ffma2(acc[3][3], xd3, wp3);
        }

        if (kc < DIM / KC - 1) {       // store next chunk into the other buffer
            float* xs2 = sbuf + ((kc + 1) & 1) * 3200;
            float* ws2 = xs2 + 2112;
            xs2[(4*lj+0)*XS + lt] = rx0.x; xs2[(4*lj+1)*XS + lt] = rx0.y;
            xs2[(4*lj+2)*XS + lt] = rx0.z; xs2[(4*lj+3)*XS + lt] = rx0.w;
            xs2[(4*lj+0)*XS + lt+64] = rx1.x; xs2[(4*lj+1)*XS + lt+64] = rx1.y;
            xs2[(4*lj+2)*XS + lt+64] = rx1.z; xs2[(4*lj+3)*XS + lt+64] = rx1.w;
            *(float4*)&ws2[wkk * WS + 4 * wc4] = rw;
            __syncthreads();
        }
    }
    __syncthreads();                   // all compute done before logits overwrite

    // ---- logits -> smem [token][expert], stride LSS ----
#pragma unroll
    for (int t = 0; t < 4; t++) {
        float2 r0 = upk2(acc[t][0]), r1 = upk2(acc[t][1]);
        float2 r2 = upk2(acc[t][2]), r3 = upk2(acc[t][3]);
        float* dst = sbuf + (size_t)(tt + t) * LSS + ee;
        *(float4*)dst       = make_float4(r0.x, r0.y, r1.x, r1.y);
        *(float4*)(dst + 4) = make_float4(r2.x, r2.y, r3.x, r3.y);
    }
    __syncthreads();

    // ---------------- routing: one thread per token (threads 0..127) ----------------
    if (tid < BT) {
        const int t = tid;
        const float* lg = sbuf + (size_t)t * LSS;

        // pass 1: max
        float mx = -1e30f;
#pragma unroll
        for (int i4 = 0; i4 < 16; i4++) {
            float4 v = *(const float4*)(lg + 4 * i4);
            mx = fmaxf(mx, fmaxf(fmaxf(v.x, v.y), fmaxf(v.z, v.w)));
        }
        // pass 2: sum of exp
        float sum = 0.f;
#pragma unroll
        for (int i4 = 0; i4 < 16; i4++) {
            float4 v = *(const float4*)(lg + 4 * i4);
            sum += expf(v.x - mx) + expf(v.y - mx) + expf(v.z - mx) + expf(v.w - mx);
        }
        // pass 3: top-8 on logits, stable (ties -> lower index first)
        float tv[8]; int ti[8];
#pragma unroll
        for (int j = 0; j < 8; j++) { tv[j] = -1e30f; ti[j] = 1 << 20; }
        for (int i4 = 0; i4 < 16; i4++) {
            float4 v4 = *(const float4*)(lg + 4 * i4);
            float vs[4] = {v4.x, v4.y, v4.z, v4.w};
#pragma unroll
            for (int c = 0; c < 4; c++) {
                float cv = vs[c];
                if (cv > tv[7]) {
                    int ci = 4 * i4 + c;
#pragma unroll
                    for (int j = 0; j < 8; j++) {
                        if (cv > tv[j]) {
                            float tf = tv[j]; int tix = ti[j];
                            tv[j] = cv; ti[j] = ci;
                            cv = tf;    ci = tix;
                        }
                    }
                }
            }
        }
        // k* via cumsum in exp-space against TAU*sum
        float qs[8];
#pragma unroll
        for (int j = 0; j < 8; j++) qs[j] = expf(tv[j] - mx);
        float thr = TAU * sum;
        float csq = 0.f; int kstar = 0;
#pragma unroll
        for (int j = 0; j < 8; j++) { csq += qs[j]; kstar += (csq < thr) ? 1 : 0; }
        if (kstar < 1) kstar = 1;

        float Q = 0.f;
#pragma unroll
        for (int j = 0; j < 8; j++) if (j < kstar) Q += qs[j];

        unsigned long long m = 0ull;
#pragma unroll
        for (int j = 0; j < 8; j++) if (j < kstar) m |= 1ull << ti[j];

        // compact probs ordered by expert index ascending (rank = prefix popcount)
        float slotv[8];
#pragma unroll
        for (int s = 0; s < 8; s++) slotv[s] = 0.f;
#pragma unroll
        for (int j = 0; j < 8; j++) {
            if (j < kstar) {
                int rank = __popcll(m & ((1ull << ti[j]) - 1ull));
                float p = qs[j] / Q;
#pragma unroll
                for (int s = 0; s < 8; s++) if (s == rank) slotv[s] = p;
            }
        }
        float* pc = g_pc + (size_t)(tok0 + t) * 8;
        *(float4*)pc       = make_float4(slotv[0], slotv[1], slotv[2], slotv[3]);
        *(float4*)(pc + 4) = make_float4(slotv[4], slotv[5], slotv[6], slotv[7]);
        smask[t] = m;
        g_mask[tok0 + t] = m;
    }
    __syncthreads();

    // ---- per-chunk expert counts, layout [e][chunk] for coalesced scan ----
    if (tid < NE) {
        int c = 0;
#pragma unroll 8
        for (int i = 0; i < BT; i++) c += (int)((smask[i] >> tid) & 1ull);
        g_cnt[tid * NCHUNK + blockIdx.x] = c;
    }
}

// =====================================================================
// Kernel 2: scan — warp-per-expert exclusive scan over 128 chunks + loss
// =====================================================================
__global__ void __launch_bounds__(1024)
k_scan(float* __restrict__ out)
{
    __shared__ float susage[NE];
    const int tid  = threadIdx.x;
    const int lane = tid & 31;
    const int w    = tid >> 5;

    for (int e = w; e < NE; e += 32) {
        int4 v = *(const int4*)&g_cnt[e * NCHUNK + lane * 4];
        int t1 = v.x + v.y, t2 = t1 + v.z, tot = t2 + v.w;
        int incl = tot;
#pragma unroll
        for (int o = 1; o < 32; o <<= 1) {
            int nv = __shfl_up_sync(0xffffffffu, incl, o);
            if (lane >= o) incl += nv;
        }
        int base = incl - tot;
        int c0 = lane * 4;
        g_off[(c0 + 0) * NE + e] = base;
        g_off[(c0 + 1) * NE + e] = base + v.x;
        g_off[(c0 + 2) * NE + e] = base + t1;
        g_off[(c0 + 3) * NE + e] = base + t2;
        int run = __shfl_sync(0xffffffffu, incl, 31);
        if (lane == 0) susage[e] = (float)(run < CAP ? run : CAP);
    }
    __syncthreads();

    if (w == 0) {
        float u0 = susage[lane], u1 = susage[lane + 32];
        float s = u0 + u1;
#pragma unroll
        for (int o = 16; o > 0; o >>= 1) s += __shfl_xor_sync(0xffffffffu, s, o);
        float mean = s / (float)NE;
        float d0 = u0 - mean, d1 = u1 - mean;
        float v = d0 * d0 + d1 * d1;
#pragma unroll
        for (int o = 16; o > 0; o >>= 1) v += __shfl_xor_sync(0xffffffffu, v, o);
        float var = v / (float)NE;
        if (lane == 0)
            out[2 * DISP_SZ] = (s > 0.f) ? var / (mean + 1e-8f) : 0.f;
    }
}

// =====================================================================
// Kernel 3: scatter — one block per chunk, masks staged in smem, ballots
// =====================================================================
__global__ void __launch_bounds__(256)
k_scatter(float* __restrict__ out)
{
    __shared__ unsigned long long sm[BT];
    __shared__ int sof[NE];

    const int c   = blockIdx.x;
    const int tid = threadIdx.x;
    const int lane = tid & 31;
    const int w    = tid >> 5;              // 8 warps

    if (tid < BT) sm[tid] = g_mask[c * BT + tid];
    if (tid < NE) sof[tid] = g_off[c * NE + tid];
    __syncthreads();

#pragma unroll
    for (int k = 0; k < 8; k++) {
        const int e = w * 8 + k;
        int base = sof[e];
        if (base >= CAP) continue;
#pragma unroll
        for (int sg = 0; sg < 4; sg++) {
            int li = sg * 32 + lane;
            unsigned long long m = sm[li];
            int bit = (int)((m >> e) & 1ull);
            unsigned bal = __ballot_sync(0xffffffffu, bit);
            int pos = base + __popc(bal & ((1u << lane) - 1u));
            if (bit && pos < CAP) {
                int t = c * BT + li;
                int rank = __popcll(m & ((1ull << e) - 1ull));
                float p = g_pc[(size_t)t * 8 + rank];
                size_t o = ((size_t)t * NE + e) * CAP + (size_t)pos;
                out[o] = 1.0f;
                out[DISP_SZ + o] = p;
            }
            base += __popc(bal);
            if (base >= CAP) break;         // warp-uniform
        }
    }
}

// ---------------- launch ----------------
extern "C" void kernel_launch(void* const* d_in, const int* in_sizes, int n_in,
                              void* d_out, int out_size)
{
    const float* x  = (const float*)d_in[0];
    const float* wg = (const float*)d_in[1];
    float* out = (float*)d_out;

    k_pre    <<<32, 256>>>(out);
    k_main   <<<GEMM_BLOCKS + NZ, 256>>>(x, wg, out);
    k_scan   <<<1, 1024>>>(out);
    k_scatter<<<NCHUNK, 256>>>(out);
}

// round 7
// speedup vs baseline: 1.8111x; 1.0974x over previous
#include <cuda_runtime.h>
#include <cstdint>
#include <cstddef>

// Problem constants
#define TOKENS   16384            // b*n = 8*2048
#define DIM      1024
#define NE       64
#define CAP      40
#define TAU      0.7f
#define DISP_SZ  ((size_t)TOKENS * NE * CAP)   // floats per output tensor

#define BT      128                  // tokens per gemm block (= chunk)
#define NCHUNK  (TOKENS / BT)        // 128
#define KC      16                   // k-chunk (double-buffered)
#define XS      132                  // xs stride (floats)
#define WS      68                   // ws stride (floats)
#define LSS     68                   // logits stride (floats)

// ---------------- static device scratch ----------------
__device__ float              g_pc  [(size_t)TOKENS * 8];     // compact probs, expert-rank order
__device__ unsigned long long g_mask[TOKENS];                 // selected-expert bitmask
__device__ int                g_cnt [NE * NCHUNK];            // [e][chunk] counts
__device__ int                g_off [NCHUNK * NE];            // [chunk][e] exclusive offsets

// ---------------- packed f32x2 helpers ----------------
static __device__ __forceinline__ unsigned long long pk2(float a, float b) {
    unsigned long long r;
    asm("mov.b64 %0, {%1, %2};" : "=l"(r) : "f"(a), "f"(b));
    return r;
}
static __device__ __forceinline__ void ffma2(unsigned long long& d,
                                             unsigned long long a,
                                             unsigned long long b) {
    asm("fma.rn.f32x2 %0, %1, %2, %0;" : "+l"(d) : "l"(a), "l"(b));
}
static __device__ __forceinline__ float2 upk2(unsigned long long a) {
    float2 r;
    asm("mov.b64 {%0, %1}, %2;" : "=f"(r.x), "=f"(r.y) : "l"(a));
    return r;
}

// =====================================================================
// Kernel A: GEMM (double-buffered) + per-thread routing.  128 blocks.
// No output-store traffic co-resident -> L1tex port all ours.
// =====================================================================
__global__ void __launch_bounds__(256)
k_gemm(const float* __restrict__ x, const float* __restrict__ wg)
{
    __shared__ float sbuf[BT * LSS];            // gemm double-buffers, then logits
    __shared__ unsigned long long smask[BT];

    const int tid = threadIdx.x;

    // buffer b at sbuf + b*3200: xs [0,2112) = [k][token], ws [2112,3200) = [k][expert]
    const int tg  = tid >> 3;          // 0..31 token group (4 tokens)
    const int eg  = tid & 7;           // 0..7  expert group (8 experts)
    const int tt  = tg * 4;
    const int ee  = eg * 8;
    const int tok0 = blockIdx.x * BT;

    const int lt  = tid >> 2;          // token for x loads (2 float4/thread)
    const int lj  = tid & 3;
    const int wkk = tid >> 4;          // k row for w load
    const int wc4 = tid & 15;

    unsigned long long acc[4][4];
#pragma unroll
    for (int i = 0; i < 4; i++)
#pragma unroll
        for (int j = 0; j < 4; j++) acc[i][j] = 0ull;

    float4 rx0, rx1, rw;
    rx0 = *(const float4*)(x + (size_t)(tok0 + lt) * DIM + 4 * lj);
    rx1 = *(const float4*)(x + (size_t)(tok0 + lt + 64) * DIM + 4 * lj);
    rw  = *(const float4*)(wg + (size_t)wkk * NE + 4 * wc4);
    {
        float* xs = sbuf;
        float* ws = sbuf + 2112;
        xs[(4*lj+0)*XS + lt] = rx0.x; xs[(4*lj+1)*XS + lt] = rx0.y;
        xs[(4*lj+2)*XS + lt] = rx0.z; xs[(4*lj+3)*XS + lt] = rx0.w;
        xs[(4*lj+0)*XS + lt+64] = rx1.x; xs[(4*lj+1)*XS + lt+64] = rx1.y;
        xs[(4*lj+2)*XS + lt+64] = rx1.z; xs[(4*lj+3)*XS + lt+64] = rx1.w;
        *(float4*)&ws[wkk * WS + 4 * wc4] = rw;
    }
    __syncthreads();

    for (int kc = 0; kc < DIM / KC; kc++) {
        const float* xs = sbuf + (kc & 1) * 3200;
        const float* ws = xs + 2112;

        if (kc < DIM / KC - 1) {
            int k0 = (kc + 1) * KC;
            rx0 = *(const float4*)(x + (size_t)(tok0 + lt) * DIM + k0 + 4 * lj);
            rx1 = *(const float4*)(x + (size_t)(tok0 + lt + 64) * DIM + k0 + 4 * lj);
            rw  = *(const float4*)(wg + (size_t)(k0 + wkk) * NE + 4 * wc4);
        }

#pragma unroll
        for (int kk = 0; kk < KC; kk++) {
            float4 xa = *(const float4*)&xs[kk * XS + tt];
            float4 wa = *(const float4*)&ws[kk * WS + ee];
            float4 wb = *(const float4*)&ws[kk * WS + ee + 4];
            unsigned long long wp0 = pk2(wa.x, wa.y), wp1 = pk2(wa.z, wa.w);
            unsigned long long wp2 = pk2(wb.x, wb.y), wp3 = pk2(wb.z, wb.w);
            unsigned long long xd0 = pk2(xa.x, xa.x), xd1 = pk2(xa.y, xa.y);
            unsigned long long xd2 = pk2(xa.z, xa.z), xd3 = pk2(xa.w, xa.w);
            ffma2(acc[0][0], xd0, wp0); ffma2(acc[0][1], xd0, wp1);
            ffma2(acc[0][2], xd0, wp2); ffma2(acc[0][3], xd0, wp3);
            ffma2(acc[1][0], xd1, wp0); ffma2(acc[1][1], xd1, wp1);
            ffma2(acc[1][2], xd1, wp2); ffma2(acc[1][3], xd1, wp3);
            ffma2(acc[2][0], xd2, wp0); ffma2(acc[2][1], xd2, wp1);
            ffma2(acc[2][2], xd2, wp2); ffma2(acc[2][3], xd2, wp3);
            ffma2(acc[3][0], xd3, wp0); ffma2(acc[3][1], xd3, wp1);
            ffma2(acc[3][2], xd3, wp2); ffma2(acc[3][3], xd3, wp3);
        }

        if (kc < DIM / KC - 1) {
            float* xs2 = sbuf + ((kc + 1) & 1) * 3200;
            float* ws2 = xs2 + 2112;
            xs2[(4*lj+0)*XS + lt] = rx0.x; xs2[(4*lj+1)*XS + lt] = rx0.y;
            xs2[(4*lj+2)*XS + lt] = rx0.z; xs2[(4*lj+3)*XS + lt] = rx0.w;
            xs2[(4*lj+0)*XS + lt+64] = rx1.x; xs2[(4*lj+1)*XS + lt+64] = rx1.y;
            xs2[(4*lj+2)*XS + lt+64] = rx1.z; xs2[(4*lj+3)*XS + lt+64] = rx1.w;
            *(float4*)&ws2[wkk * WS + 4 * wc4] = rw;
            __syncthreads();
        }
    }
    __syncthreads();

    // ---- logits -> smem [token][expert] ----
#pragma unroll
    for (int t = 0; t < 4; t++) {
        float2 r0 = upk2(acc[t][0]), r1 = upk2(acc[t][1]);
        float2 r2 = upk2(acc[t][2]), r3 = upk2(acc[t][3]);
        float* dst = sbuf + (size_t)(tt + t) * LSS + ee;
        *(float4*)dst       = make_float4(r0.x, r0.y, r1.x, r1.y);
        *(float4*)(dst + 4) = make_float4(r2.x, r2.y, r3.x, r3.y);
    }
    __syncthreads();

    // ---- routing: one thread per token ----
    if (tid < BT) {
        const int t = tid;
        const float* lg = sbuf + (size_t)t * LSS;

        float mx = -1e30f;
#pragma unroll
        for (int i4 = 0; i4 < 16; i4++) {
            float4 v = *(const float4*)(lg + 4 * i4);
            mx = fmaxf(mx, fmaxf(fmaxf(v.x, v.y), fmaxf(v.z, v.w)));
        }
        float sum = 0.f;
#pragma unroll
        for (int i4 = 0; i4 < 16; i4++) {
            float4 v = *(const float4*)(lg + 4 * i4);
            sum += expf(v.x - mx) + expf(v.y - mx) + expf(v.z - mx) + expf(v.w - mx);
        }
        float tv[8]; int ti[8];
#pragma unroll
        for (int j = 0; j < 8; j++) { tv[j] = -1e30f; ti[j] = 1 << 20; }
        for (int i4 = 0; i4 < 16; i4++) {
            float4 v4 = *(const float4*)(lg + 4 * i4);
            float vs[4] = {v4.x, v4.y, v4.z, v4.w};
#pragma unroll
            for (int c = 0; c < 4; c++) {
                float cv = vs[c];
                if (cv > tv[7]) {
                    int ci = 4 * i4 + c;
#pragma unroll
                    for (int j = 0; j < 8; j++) {
                        if (cv > tv[j]) {
                            float tf = tv[j]; int tix = ti[j];
                            tv[j] = cv; ti[j] = ci;
                            cv = tf;    ci = tix;
                        }
                    }
                }
            }
        }
        float qs[8];
#pragma unroll
        for (int j = 0; j < 8; j++) qs[j] = expf(tv[j] - mx);
        float thr = TAU * sum;
        float csq = 0.f; int kstar = 0;
#pragma unroll
        for (int j = 0; j < 8; j++) { csq += qs[j]; kstar += (csq < thr) ? 1 : 0; }
        if (kstar < 1) kstar = 1;

        float Q = 0.f;
#pragma unroll
        for (int j = 0; j < 8; j++) if (j < kstar) Q += qs[j];

        unsigned long long m = 0ull;
#pragma unroll
        for (int j = 0; j < 8; j++) if (j < kstar) m |= 1ull << ti[j];

        float slotv[8];
#pragma unroll
        for (int s = 0; s < 8; s++) slotv[s] = 0.f;
#pragma unroll
        for (int j = 0; j < 8; j++) {
            if (j < kstar) {
                int rank = __popcll(m & ((1ull << ti[j]) - 1ull));
                float p = qs[j] / Q;
#pragma unroll
                for (int s = 0; s < 8; s++) if (s == rank) slotv[s] = p;
            }
        }
        float* pc = g_pc + (size_t)(tok0 + t) * 8;
        *(float4*)pc       = make_float4(slotv[0], slotv[1], slotv[2], slotv[3]);
        *(float4*)(pc + 4) = make_float4(slotv[4], slotv[5], slotv[6], slotv[7]);
        smask[t] = m;
        g_mask[tok0 + t] = m;
    }
    __syncthreads();

    if (tid < NE) {
        int c = 0;
#pragma unroll 8
        for (int i = 0; i < BT; i++) c += (int)((smask[i] >> tid) & 1ull);
        g_cnt[tid * NCHUNK + blockIdx.x] = c;
    }
}

// =====================================================================
// Kernel B: pure zero-fill of an output range [lo4, hi4) in float4 units.
// Full-chip grid, contiguous slab per block. Launched 3x (thirds) so the
// 3rd instance sits at absolute launch #6 -> ncu profiles the store phase.
// =====================================================================
#define ZGRID 296
__global__ void __launch_bounds__(256)
k_zero(float* __restrict__ out, size_t lo4, size_t hi4)
{
    const size_t span = hi4 - lo4;
    const size_t per = (span + ZGRID - 1) / ZGRID;
    size_t lo = lo4 + (size_t)blockIdx.x * per;
    size_t hi = lo + per; if (hi > hi4) hi = hi4;
    float4 z = make_float4(0.f, 0.f, 0.f, 0.f);
    float4* o4 = (float4*)out;
    for (size_t i = lo + threadIdx.x; i < hi; i += 256) o4[i] = z;
}

// =====================================================================
// Kernel C: scan — warp-per-expert exclusive scan over 128 chunks + loss
// =====================================================================
__global__ void __launch_bounds__(1024)
k_scan(float* __restrict__ out)
{
    __shared__ float susage[NE];
    const int tid  = threadIdx.x;
    const int lane = tid & 31;
    const int w    = tid >> 5;

    for (int e = w; e < NE; e += 32) {
        int4 v = *(const int4*)&g_cnt[e * NCHUNK + lane * 4];
        int t1 = v.x + v.y, t2 = t1 + v.z, tot = t2 + v.w;
        int incl = tot;
#pragma unroll
        for (int o = 1; o < 32; o <<= 1) {
            int nv = __shfl_up_sync(0xffffffffu, incl, o);
            if (lane >= o) incl += nv;
        }
        int base = incl - tot;
        int c0 = lane * 4;
        g_off[(c0 + 0) * NE + e] = base;
        g_off[(c0 + 1) * NE + e] = base + v.x;
        g_off[(c0 + 2) * NE + e] = base + t1;
        g_off[(c0 + 3) * NE + e] = base + t2;
        int run = __shfl_sync(0xffffffffu, incl, 31);
        if (lane == 0) susage[e] = (float)(run < CAP ? run : CAP);
    }
    __syncthreads();

    if (w == 0) {
        float u0 = susage[lane], u1 = susage[lane + 32];
        float s = u0 + u1;
#pragma unroll
        for (int o = 16; o > 0; o >>= 1) s += __shfl_xor_sync(0xffffffffu, s, o);
        float mean = s / (float)NE;
        float d0 = u0 - mean, d1 = u1 - mean;
        float v = d0 * d0 + d1 * d1;
#pragma unroll
        for (int o = 16; o > 0; o >>= 1) v += __shfl_xor_sync(0xffffffffu, v, o);
        float var = v / (float)NE;
        if (lane == 0)
            out[2 * DISP_SZ] = (s > 0.f) ? var / (mean + 1e-8f) : 0.f;
    }
}

// =====================================================================
// Kernel D: scatter — block per chunk, 16 warps x 4 experts, ballots
// =====================================================================
__global__ void __launch_bounds__(512)
k_scatter(float* __restrict__ out)
{
    __shared__ unsigned long long sm[BT];
    __shared__ int sof[NE];

    const int c    = blockIdx.x;
    const int tid  = threadIdx.x;
    const int lane = tid & 31;
    const int w    = tid >> 5;              // 16 warps

    if (tid < BT) sm[tid] = g_mask[c * BT + tid];
    if (tid < NE) sof[tid] = g_off[c * NE + tid];
    __syncthreads();

#pragma unroll
    for (int k = 0; k < 4; k++) {
        const int e = w * 4 + k;
        int base = sof[e];
        if (base >= CAP) continue;
#pragma unroll
        for (int sg = 0; sg < 4; sg++) {
            int li = sg * 32 + lane;
            unsigned long long m = sm[li];
            int bit = (int)((m >> e) & 1ull);
            unsigned bal = __ballot_sync(0xffffffffu, bit);
            int pos = base + __popc(bal & ((1u << lane) - 1u));
            if (bit && pos < CAP) {
                int t = c * BT + li;
                int rank = __popcll(m & ((1ull << e) - 1ull));
                float p = g_pc[(size_t)t * 8 + rank];
                size_t o = ((size_t)t * NE + e) * CAP + (size_t)pos;
                out[o] = 1.0f;
                out[DISP_SZ + o] = p;
            }
            base += __popc(bal);
            if (base >= CAP) break;         // warp-uniform
        }
    }
}

// ---------------- launch ----------------
extern "C" void kernel_launch(void* const* d_in, const int* in_sizes, int n_in,
                              void* d_out, int out_size)
{
    const float* x  = (const float*)d_in[0];
    const float* wg = (const float*)d_in[1];
    float* out = (float*)d_out;

    const size_t nz4 = (2 * DISP_SZ) / 4;     // total float4s to zero
    const size_t third = nz4 / 3;             // nz4 = 20971520, divisible? 20971520/3 no -> handle remainder in last

    k_gemm   <<<NCHUNK, 256>>>(x, wg);                          // launch 1 (abs #3)
    k_zero   <<<ZGRID, 256>>>(out, 0,         third);           // launch 2 (abs #4)
    k_zero   <<<ZGRID, 256>>>(out, third,     2 * third);       // launch 3 (abs #5)
    k_zero   <<<ZGRID, 256>>>(out, 2 * third, nz4);             // launch 4 (abs #6) <- ncu
    k_scan   <<<1, 1024>>>(out);
    k_scatter<<<NCHUNK, 512>>>(out);
}